// round 11
// baseline (speedup 1.0000x reference)
#include <cuda_runtime.h>

#define TH 16
#define TW 64
#define NT 384
#define HIMG 512
#define WIMG 512
#define SAW 68   // padded row stride for s_a
#define SCW 36   // padded row stride for s_c (half-res chroma)

__constant__ float c_D[64];   // DCT matrix, row-major

__device__ __forceinline__ float dot8(const float4 a0, const float4 a1,
                                      const float4 b0, const float4 b1) {
    return fmaf(a1.w, b1.w, fmaf(a1.z, b1.z, fmaf(a1.y, b1.y,
           fmaf(a1.x, b1.x, fmaf(a0.w, b0.w, fmaf(a0.z, b0.z,
           fmaf(a0.y, b0.y, a0.x * b0.x)))))));
}

__global__ __launch_bounds__(NT, 3) void jpeg_kernel(
    const float* __restrict__ in, const float* __restrict__ quant,
    const float* __restrict__ dct, float* __restrict__ out)
{
    __shared__ __align__(16) float s_a[3][TH][SAW];   // X / T1^T / W / Z
    __shared__ __align__(16) float s_c[2][TH/2][SCW]; // half-res chroma
    __shared__ __align__(16) float s_qt[3][8][8];     // q transposed
    __shared__ __align__(16) float s_rqt[3][8][8];    // 1/q transposed

    const int tid = threadIdx.x;
    const int b   = blockIdx.z;
    const int ty0 = blockIdx.y * TH;
    const int tx0 = blockIdx.x * TW;

    // ---- tables (transposed quant) ----
    if (tid < 192) {
        int i = tid;
        float qv = rintf(quant[i] * 255.0f);
        float q1 = rintf((qv * 50.0f + 50.0f) / 100.0f);
        float q  = fminf(fmaxf(q1, 1.0f), 255.0f);
        int ci = i >> 6, ri = (i >> 3) & 7, li = i & 7;
        s_qt[ci][li][ri]  = q;
        s_rqt[ci][li][ri] = 1.0f / q;
    }

    const size_t plane = (size_t)HIMG * WIMG;
    const float* base  = in  + (size_t)b * 3 * plane;
    float*       obase = out + (size_t)b * 3 * plane;

    // ---- phase 1 (256 threads): 4x1 strips; chroma 2x2 mean via shuffle ----
    if (tid < 256) {
        const int sy = tid >> 4;
        const int sx = tid & 15;
        const int px = sx * 4;
        const size_t idx = (size_t)(ty0 + sy) * WIMG + (tx0 + px);

        const float4 r4 = *(const float4*)&base[idx];
        const float4 g4 = *(const float4*)&base[plane + idx];
        const float4 b4 = *(const float4*)&base[2*plane + idx];

        float R[4] = {255.0f*r4.x, 255.0f*r4.y, 255.0f*r4.z, 255.0f*r4.w};
        float G[4] = {255.0f*g4.x, 255.0f*g4.y, 255.0f*g4.z, 255.0f*g4.w};
        float B[4] = {255.0f*b4.x, 255.0f*b4.y, 255.0f*b4.z, 255.0f*b4.w};

        #define YV(R_,G_,B_)  fmaf(0.114f,(B_), fmaf(0.587f,(G_), 0.299f*(R_)))
        #define CBV(R_,G_,B_) (fmaf(0.5f,(B_),  fmaf(-0.331264108f,(G_), -0.168735892f*(R_))) + 128.0f)
        #define CRV(R_,G_,B_) (fmaf(-0.081312411f,(B_), fmaf(-0.418687589f,(G_), 0.5f*(R_))) + 128.0f)
        #define CL(v) fminf(fmaxf((v), 0.0f), 255.0f)

        float Y[4], CB[4], CR[4];
        #pragma unroll
        for (int e = 0; e < 4; e++) {
            Y[e]  = CL(YV(R[e], G[e], B[e])) - 128.0f;
            CB[e] = CL(CBV(R[e], G[e], B[e]));
            CR[e] = CL(CRV(R[e], G[e], B[e]));
        }
        *(float4*)&s_a[0][sy][px] = make_float4(Y[0], Y[1], Y[2], Y[3]);

        float pcb0 = __shfl_xor_sync(0xffffffffu, CB[0], 16);
        float pcb1 = __shfl_xor_sync(0xffffffffu, CB[1], 16);
        float pcb2 = __shfl_xor_sync(0xffffffffu, CB[2], 16);
        float pcb3 = __shfl_xor_sync(0xffffffffu, CB[3], 16);
        float pcr0 = __shfl_xor_sync(0xffffffffu, CR[0], 16);
        float pcr1 = __shfl_xor_sync(0xffffffffu, CR[1], 16);
        float pcr2 = __shfl_xor_sync(0xffffffffu, CR[2], 16);
        float pcr3 = __shfl_xor_sync(0xffffffffu, CR[3], 16);
        if ((sy & 1) == 0) {
            float cbm0 = 0.25f * (((CB[0] + CB[1]) + pcb0) + pcb1) - 128.0f;
            float cbm1 = 0.25f * (((CB[2] + CB[3]) + pcb2) + pcb3) - 128.0f;
            float crm0 = 0.25f * (((CR[0] + CR[1]) + pcr0) + pcr1) - 128.0f;
            float crm1 = 0.25f * (((CR[2] + CR[3]) + pcr2) + pcr3) - 128.0f;
            *(float2*)&s_c[0][sy >> 1][sx*2] = make_float2(cbm0, cbm1);
            *(float2*)&s_c[1][sy >> 1][sx*2] = make_float2(crm0, crm1);
        }
    }
    __syncthreads();

    // ---- assignment: 48 units * 8 threads; thread owns ONE row r ----
    const int unit = tid >> 3;    // 0..47
    const int r    = tid & 7;     // row / column index
    int c, by, bx;
    if (unit < 16) { c = 0; by = unit >> 3; bx = unit & 7; }
    else { int t = unit - 16; c = 1 + (t >> 4); int rem = t & 15; by = rem >> 3; bx = rem & 7; }
    float* pW = &s_a[c][by*8][bx*8];

    // ==== stage A: T1 = X*D^T (luma) / T1c = Xh*E^T (chroma); write transposed ====
    {
        float A[8];
        if (c == 0) {
            const float4 x0 = *(const float4*)(pW + r*SAW);
            const float4 x1 = *(const float4*)(pW + r*SAW + 4);
            #pragma unroll
            for (int l = 0; l < 8; l++) {
                const float4 d0 = *(const float4*)&c_D[l*8];
                const float4 d1 = *(const float4*)&c_D[l*8 + 4];
                A[l] = dot8(x0, x1, d0, d1);
            }
            __syncwarp();
            #pragma unroll
            for (int j = 0; j < 8; j++)
                pW[j*SAW + r] = A[j];
        } else {
            float4 xh = make_float4(0.f, 0.f, 0.f, 0.f);
            if (r < 4) xh = *(const float4*)(&s_c[c-1][by*4 + r][bx*4]);
            #pragma unroll
            for (int l = 0; l < 8; l++) {
                const float4 d0 = *(const float4*)&c_D[l*8];
                const float4 d1 = *(const float4*)&c_D[l*8 + 4];
                float e0 = d0.x + d0.y, e1 = d0.z + d0.w;
                float e2 = d1.x + d1.y, e3 = d1.z + d1.w;
                A[l] = fmaf(xh.w, e3, fmaf(xh.z, e2, fmaf(xh.y, e1, xh.x * e0)));
            }
            __syncwarp();
            if (r < 4) {
                #pragma unroll
                for (int j = 0; j < 8; j++)
                    pW[j*SAW + r] = A[j];
            }
        }
    }
    __syncwarp();

    // ==== stage B: row r of Y2^T = T1^T * D^T (or * E^T), quant/dequant ====
    float Yq[8];
    {
        if (c == 0) {
            const float4 a0 = *(const float4*)(pW + r*SAW);
            const float4 a1 = *(const float4*)(pW + r*SAW + 4);
            #pragma unroll
            for (int l = 0; l < 8; l++) {
                const float4 d0 = *(const float4*)&c_D[l*8];
                const float4 d1 = *(const float4*)&c_D[l*8 + 4];
                Yq[l] = dot8(a0, a1, d0, d1);
            }
        } else {
            const float4 a0 = *(const float4*)(pW + r*SAW);   // 4-wide row of T1c^T
            #pragma unroll
            for (int l = 0; l < 8; l++) {
                const float4 d0 = *(const float4*)&c_D[l*8];
                const float4 d1 = *(const float4*)&c_D[l*8 + 4];
                float e0 = d0.x + d0.y, e1 = d0.z + d0.w;
                float e2 = d1.x + d1.y, e3 = d1.z + d1.w;
                Yq[l] = fmaf(a0.w, e3, fmaf(a0.z, e2, fmaf(a0.y, e1, a0.x * e0)));
            }
        }
        const float4 q0  = *(const float4*)&s_qt[c][r][0];
        const float4 q1  = *(const float4*)&s_qt[c][r][4];
        const float4 rq0 = *(const float4*)&s_rqt[c][r][0];
        const float4 rq1 = *(const float4*)&s_rqt[c][r][4];
        Yq[0] = rintf(rintf(Yq[0]*rq0.x)*q0.x);  Yq[1] = rintf(rintf(Yq[1]*rq0.y)*q0.y);
        Yq[2] = rintf(rintf(Yq[2]*rq0.z)*q0.z);  Yq[3] = rintf(rintf(Yq[3]*rq0.w)*q0.w);
        Yq[4] = rintf(rintf(Yq[4]*rq1.x)*q1.x);  Yq[5] = rintf(rintf(Yq[5]*rq1.y)*q1.y);
        Yq[6] = rintf(rintf(Yq[6]*rq1.z)*q1.z);  Yq[7] = rintf(rintf(Yq[7]*rq1.w)*q1.w);
    }
    __syncwarp();   // all T1^T reads done -> safe to overwrite

    // ==== stage C: G row = Y2'^T * D; write transposed (W = D^T*Y2') ====
    {
        float G[8];
        #pragma unroll
        for (int l = 0; l < 8; l++) G[l] = 0.0f;
        #pragma unroll
        for (int k = 0; k < 8; k++) {
            const float4 d0 = *(const float4*)&c_D[k*8];
            const float4 d1 = *(const float4*)&c_D[k*8 + 4];
            const float t = Yq[k];
            G[0] = fmaf(t, d0.x, G[0]);  G[1] = fmaf(t, d0.y, G[1]);
            G[2] = fmaf(t, d0.z, G[2]);  G[3] = fmaf(t, d0.w, G[3]);
            G[4] = fmaf(t, d1.x, G[4]);  G[5] = fmaf(t, d1.y, G[5]);
            G[6] = fmaf(t, d1.z, G[6]);  G[7] = fmaf(t, d1.w, G[7]);
        }
        #pragma unroll
        for (int j = 0; j < 8; j++)
            pW[j*SAW + r] = G[j];
    }
    __syncwarp();

    // ==== stage D: Z row = W * D (row-local), +off, write normal ====
    {
        float w[8];
        *(float4*)&w[0] = *(const float4*)(pW + r*SAW);
        *(float4*)&w[4] = *(const float4*)(pW + r*SAW + 4);
        float Z[8];
        #pragma unroll
        for (int l = 0; l < 8; l++) Z[l] = 0.0f;
        #pragma unroll
        for (int k = 0; k < 8; k++) {
            const float4 d0 = *(const float4*)&c_D[k*8];
            const float4 d1 = *(const float4*)&c_D[k*8 + 4];
            const float t = w[k];
            Z[0] = fmaf(t, d0.x, Z[0]);  Z[1] = fmaf(t, d0.y, Z[1]);
            Z[2] = fmaf(t, d0.z, Z[2]);  Z[3] = fmaf(t, d0.w, Z[3]);
            Z[4] = fmaf(t, d1.x, Z[4]);  Z[5] = fmaf(t, d1.y, Z[5]);
            Z[6] = fmaf(t, d1.z, Z[6]);  Z[7] = fmaf(t, d1.w, Z[7]);
        }
        const float off = (c == 0) ? 128.0f : 0.0f;
        #pragma unroll
        for (int l = 0; l < 8; l++) Z[l] += off;
        // own-row read/write only: no barrier needed before store
        *(float4*)(pW + r*SAW)     = make_float4(Z[0], Z[1], Z[2], Z[3]);
        *(float4*)(pW + r*SAW + 4) = make_float4(Z[4], Z[5], Z[6], Z[7]);
    }
    __syncthreads();

    // ---- phase 5 (256 threads): YCbCr -> RGB, clip, round, store ----
    if (tid < 256) {
        const int py  = tid >> 4;
        const int px4 = (tid & 15) * 4;
        const float4 yv  = *(const float4*)&s_a[0][py][px4];
        const float4 cbv = *(const float4*)&s_a[1][py][px4];
        const float4 crv = *(const float4*)&s_a[2][py][px4];

        #define FIN(v) (rintf(fminf(fmaxf((v), 0.0f), 255.0f)) * (1.0f/255.0f))
        float4 R, G, Bv;
        R.x = FIN(fmaf(1.402f, crv.x, yv.x));  R.y = FIN(fmaf(1.402f, crv.y, yv.y));
        R.z = FIN(fmaf(1.402f, crv.z, yv.z));  R.w = FIN(fmaf(1.402f, crv.w, yv.w));
        G.x = FIN(fmaf(-0.714136286f, crv.x, fmaf(-0.344136286f, cbv.x, yv.x)));
        G.y = FIN(fmaf(-0.714136286f, crv.y, fmaf(-0.344136286f, cbv.y, yv.y)));
        G.z = FIN(fmaf(-0.714136286f, crv.z, fmaf(-0.344136286f, cbv.z, yv.z)));
        G.w = FIN(fmaf(-0.714136286f, crv.w, fmaf(-0.344136286f, cbv.w, yv.w)));
        Bv.x = FIN(fmaf(1.772f, cbv.x, yv.x)); Bv.y = FIN(fmaf(1.772f, cbv.y, yv.y));
        Bv.z = FIN(fmaf(1.772f, cbv.z, yv.z)); Bv.w = FIN(fmaf(1.772f, cbv.w, yv.w));

        const size_t idx = (size_t)(ty0 + py) * WIMG + (tx0 + px4);
        *(float4*)&obase[idx]           = R;
        *(float4*)&obase[plane + idx]   = G;
        *(float4*)&obase[2*plane + idx] = Bv;
    }
}

extern "C" void kernel_launch(void* const* d_in, const int* in_sizes, int n_in,
                              void* d_out, int out_size)
{
    const float* x = nullptr;
    const float* q = nullptr;
    const float* d = nullptr;
    int nimg = 0;
    for (int i = 0; i < n_in; i++) {
        if (in_sizes[i] == 192)      q = (const float*)d_in[i];
        else if (in_sizes[i] == 64)  d = (const float*)d_in[i];
        else { x = (const float*)d_in[i]; nimg = in_sizes[i] / (3 * HIMG * WIMG); }
    }
    cudaMemcpyToSymbolAsync(c_D, d, 64 * sizeof(float), 0,
                            cudaMemcpyDeviceToDevice, 0);
    dim3 grid(WIMG / TW, HIMG / TH, nimg);
    jpeg_kernel<<<grid, NT>>>(x, q, d, (float*)d_out);
}